// round 5
// baseline (speedup 1.0000x reference)
#include <cuda_runtime.h>
#include <cuda_fp16.h>
#include <cstdint>

#define BB      4
#define CINC    64
#define COUTC   64
#define KNB     16
#define NN      32768
#define PTS     128       // points per CTA (= GEMM M)
#define VROW    260       // V row stride (words): A-frag LDS conflict-free
#define WSTR    72        // W4 row stride (words): B-frag LDS conflict-free
#define THREADS 1024

// ---- scratch (no allocations allowed) ----
__device__ __half g_featH[(size_t)BB * NN * CINC];   // [b][n][c]  fp16, 16.8MB
__device__ float4 g_posT [(size_t)BB * NN];          // [b][n] xyz_
__device__ int    g_nbT  [(size_t)BB * NN * KNB];    // [b][n][k]

__device__ __forceinline__ uint32_t f32_to_tf32(float x) {
    uint32_t r;
    asm("cvt.rna.tf32.f32 %0, %1;" : "=r"(r) : "f"(x));
    return r;
}

// m16n8k8 tf32 MMA (sm_80+ PTX, HMMA on sm_103a)
__device__ __forceinline__ void mma_tf32(float d[4],
    uint32_t a0, uint32_t a1, uint32_t a2, uint32_t a3,
    uint32_t b0, uint32_t b1)
{
    asm volatile(
        "mma.sync.aligned.m16n8k8.row.col.f32.tf32.tf32.f32 "
        "{%0,%1,%2,%3}, {%4,%5,%6,%7}, {%8,%9}, {%0,%1,%2,%3};"
        : "+f"(d[0]), "+f"(d[1]), "+f"(d[2]), "+f"(d[3])
        : "r"(a0), "r"(a1), "r"(a2), "r"(a3), "r"(b0), "r"(b1));
}

// smem layout (32-bit words)
static constexpr int SW_W4   = 0;                       // [256][WSTR]
static constexpr int SW_VS   = 256 * WSTR;              // [PTS][VROW]
static constexpr int SW_BIAS = SW_VS + PTS * VROW;      // [64]
static constexpr int SMEM_WORDS = SW_BIAS + 64;
static constexpr int SMEM_BYTES = SMEM_WORDS * 4;       // ~207.6 KB

// ---------------------------------------------------------------------------
// Kernel 1a: transpose features [B][CIN][N] -> [B][N][CIN] (fp16 out)
// ---------------------------------------------------------------------------
__global__ void __launch_bounds__(256) transpose_feat(const float4* __restrict__ f4) {
    __shared__ float tile[64][65];
    const int b  = blockIdx.y;
    const int n0 = blockIdx.x * 64;
    const int tx = threadIdx.x & 15;       // n-quad (load) / channel-quad (store)
    const int ty = threadIdx.x >> 4;       // 0..15
    const float4* src = f4 + (size_t)b * CINC * (NN / 4) + (n0 >> 2);
    #pragma unroll
    for (int cc = ty; cc < 64; cc += 16) {
        float4 v = __ldg(&src[(size_t)cc * (NN / 4) + tx]);
        tile[4 * tx + 0][cc] = v.x;
        tile[4 * tx + 1][cc] = v.y;
        tile[4 * tx + 2][cc] = v.z;
        tile[4 * tx + 3][cc] = v.w;
    }
    __syncthreads();
    // store: row rr (point n0+rr), channels 4tx..4tx+3 as 2x half2 (uint2)
    uint2* dst = (uint2*)(g_featH + ((size_t)b * NN + n0) * CINC);
    #pragma unroll
    for (int rr = ty; rr < 64; rr += 16) {
        __half2 h0 = __floats2half2_rn(tile[rr][4 * tx + 0], tile[rr][4 * tx + 1]);
        __half2 h1 = __floats2half2_rn(tile[rr][4 * tx + 2], tile[rr][4 * tx + 3]);
        uint2 u;
        u.x = *(uint32_t*)&h0;
        u.y = *(uint32_t*)&h1;
        dst[(size_t)rr * 16 + tx] = u;
    }
}

// ---------------------------------------------------------------------------
// Kernel 1b: positions -> float4 rows; neighborhood -> [b][n][k]
// ---------------------------------------------------------------------------
__global__ void prep_pos_nb(const float* __restrict__ pos, const int* __restrict__ nb) {
    const int t = blockIdx.x * blockDim.x + threadIdx.x;   // over B*N
    const int b = t / NN;
    const int n = t - b * NN;
    const float* p = pos + (size_t)b * 3 * NN;
    g_posT[t] = make_float4(p[n], p[NN + n], p[2 * NN + n], 0.f);
    const int* s = nb + (size_t)b * KNB * NN;
    int* d = g_nbT + (size_t)t * KNB;
    #pragma unroll
    for (int k = 0; k < KNB; k++) d[k] = s[(size_t)k * NN + n];
}

// ---------------------------------------------------------------------------
// Main: gather(fp16)+reduce(fp32) -> V(tf32, smem) -> mma.sync tf32 GEMM
//   V[p][cc], cc = d*64 + c : d=0..2 -> S[d][c], d=3 -> fsum[c]
//   W4[cc][o] = [theta(192 rows); wb(64 rows)]
// ---------------------------------------------------------------------------
__global__ void __launch_bounds__(THREADS, 1) flexconv_main(
    const float* __restrict__ wt,    // [3][CIN][COUT]
    const float* __restrict__ wb,    // [CIN][COUT]
    const float* __restrict__ bias,  // [COUT]
    float* __restrict__ out)         // [B][COUT][N]
{
    extern __shared__ uint32_t smw[];
    uint32_t* W4s = smw + SW_W4;
    uint32_t* Vs  = smw + SW_VS;
    float*    bs  = (float*)(smw + SW_BIAS);

    const int tid = threadIdx.x;
    const int w   = tid >> 5, l = tid & 31;
    const int b   = blockIdx.y;
    const int n0  = blockIdx.x * PTS;

    if (tid < COUTC) bs[tid] = bias[tid];

    // stage W4 -> [k][o] with stride WSTR, converted to tf32 (coalesced over o)
    #pragma unroll
    for (int it = 0; it < (256 * 64) / THREADS; it++) {
        int t = tid + it * THREADS;
        int k = t >> 6, o = t & 63;
        float v = (k < 192) ? wt[t] : wb[t - 192 * 64];
        W4s[k * WSTR + o] = f32_to_tf32(v);
    }

    // ---------------- phase 1: gather + neighbor reduction ----------------
    const __half2* featH2 = (const __half2*)g_featH;      // [(b*N+idx)*32 + l]
    const float4*  posT   = g_posT + (size_t)b * NN;

    #pragma unroll 1
    for (int i = 0; i < 4; i++) {                         // 32 warps x 4 points
        const int p = w * 4 + i;
        const int n = n0 + p;
        const int* nbrow = g_nbT + ((size_t)b * NN + n) * KNB;
        int myidx = nbrow[l & 15];
        const float4 ps = __ldg(&posT[n]);
        float2 v0 = make_float2(0.f, 0.f), v1 = v0, v2 = v0, v3 = v0;
        #pragma unroll
        for (int k = 0; k < KNB; k++) {
            int idx = __shfl_sync(0xffffffffu, myidx, k);
            float4 pg = __ldg(&posT[idx]);
            __half2 fh = __ldg(&featH2[((size_t)b * NN + idx) * 32 + l]);
            float2 fv = __half22float2(fh);
            float dx = pg.x - ps.x, dy = pg.y - ps.y, dz = pg.z - ps.z;
            v0.x += dx * fv.x; v0.y += dx * fv.y;
            v1.x += dy * fv.x; v1.y += dy * fv.y;
            v2.x += dz * fv.x; v2.y += dz * fv.y;
            v3.x += fv.x;      v3.y += fv.y;
        }
        uint32_t* vrow = Vs + p * VROW;                   // cc = d*64 + 2l
        vrow[0 * 64 + 2 * l] = f32_to_tf32(v0.x);  vrow[0 * 64 + 2 * l + 1] = f32_to_tf32(v0.y);
        vrow[1 * 64 + 2 * l] = f32_to_tf32(v1.x);  vrow[1 * 64 + 2 * l + 1] = f32_to_tf32(v1.y);
        vrow[2 * 64 + 2 * l] = f32_to_tf32(v2.x);  vrow[2 * 64 + 2 * l + 1] = f32_to_tf32(v2.y);
        vrow[3 * 64 + 2 * l] = f32_to_tf32(v3.x);  vrow[3 * 64 + 2 * l + 1] = f32_to_tf32(v3.y);
    }
    __syncthreads();

    // ---------------- phase 2: tf32 tensor GEMM 128x64x256 -----------------
    // 32 warps: warp tile m16 x n16, full K. 2 n8-tiles per warp.
    const int mw = w & 7;            // M tile index (8 tiles x 16 rows)
    const int nq = w >> 3;           // N quarter index (4 x 16 cols)
    const int r  = l >> 2, c = l & 3;

    float acc[2][4];
    #pragma unroll
    for (int t = 0; t < 2; t++)
        acc[t][0] = acc[t][1] = acc[t][2] = acc[t][3] = 0.f;

    const uint32_t* Va = Vs + (16 * mw + r) * VROW + c;   // +0 / +8*VROW rows
    const uint32_t* Wb = W4s + 16 * nq + r;               // [k][o]

    #pragma unroll 8
    for (int k0 = 0; k0 < 256; k0 += 8) {
        uint32_t a0 = Va[k0];
        uint32_t a1 = Va[8 * VROW + k0];
        uint32_t a2 = Va[k0 + 4];
        uint32_t a3 = Va[8 * VROW + k0 + 4];
        const uint32_t* wk0 = Wb + (k0 + c) * WSTR;
        const uint32_t* wk1 = Wb + (k0 + c + 4) * WSTR;
        #pragma unroll
        for (int t = 0; t < 2; t++)
            mma_tf32(acc[t], a0, a1, a2, a3, wk0[8 * t], wk1[8 * t]);
    }

    // ---------------- epilogue: bias + store --------------------------------
    float* op = out + (size_t)b * COUTC * NN + n0 + 16 * mw + r;
    #pragma unroll
    for (int t = 0; t < 2; t++) {
        int o0 = 16 * nq + 8 * t + 2 * c;
        float bv0 = bs[o0], bv1 = bs[o0 + 1];
        op[(size_t)o0 * NN]           = acc[t][0] + bv0;
        op[(size_t)(o0 + 1) * NN]     = acc[t][1] + bv1;
        op[(size_t)o0 * NN + 8]       = acc[t][2] + bv0;
        op[(size_t)(o0 + 1) * NN + 8] = acc[t][3] + bv1;
    }
}

// ---------------------------------------------------------------------------
extern "C" void kernel_launch(void* const* d_in, const int* in_sizes, int n_in,
                              void* d_out, int out_size) {
    const float* feat = (const float*)d_in[0];   // [B][CIN][N]
    const float* wt   = (const float*)d_in[1];   // [3][CIN][COUT]
    const float* wb   = (const float*)d_in[2];   // [CIN][COUT]
    const float* bias = (const float*)d_in[3];   // [COUT]
    const int*   nb   = (const int*)  d_in[4];   // [B][K][N]
    const float* pos  = (const float*)d_in[5];   // [B][3][N]
    float* out = (float*)d_out;

    transpose_feat<<<dim3(NN / 64, BB), 256>>>((const float4*)feat);
    prep_pos_nb<<<(BB * NN) / 256, 256>>>(pos, nb);

    cudaFuncSetAttribute(flexconv_main,
                         cudaFuncAttributeMaxDynamicSharedMemorySize, SMEM_BYTES);
    flexconv_main<<<dim3(NN / PTS, BB), THREADS, SMEM_BYTES>>>(wt, wb, bias, out);
}